// round 14
// baseline (speedup 1.0000x reference)
#include <cuda_runtime.h>

#define BB 64
#define NN 4096
#define DD 128
#define KK 8
#define SCALE 0.08838834764831845f
#define EPSA 1e-8f
#define LNE 1e-5f
#define CH 16   /* chunks per batch in pass kernel */

typedef unsigned long long u64;

// f32x2 packed math (sm_103a); b64 register = {lo,hi} f32 lanes
#define FMA2(d,a,b,c) asm("fma.rn.f32x2 %0,%1,%2,%3;" : "=l"(d) : "l"(a), "l"(b), "l"(c))
#define ADD2(d,a,b)   asm("add.rn.f32x2 %0,%1,%2;"    : "=l"(d) : "l"(a), "l"(b))
#define PACK2(d,lo,hi)   asm("mov.b64 %0,{%1,%2};" : "=l"(d) : "f"(lo), "f"(hi))
#define UNPACK2(lo,hi,s) asm("mov.b64 {%0,%1},%2;" : "=f"(lo), "=f"(hi) : "l"(s))

// -------- scratch (device globals; no allocation allowed) --------
__device__ float g_slots[BB*KK*DD];
__device__ float g_qkg[BB*KK*DD];
__device__ float g_sg[BB*KK];
__device__ float g_cb[BB*KK];
__device__ float g_Up[BB*CH*KK*DD];   // per-chunk partials (deterministic reduce)
__device__ float g_Sp[BB*CH*KK];
__device__ float g_Tp[BB*CH*KK];

// -------- helpers --------
__device__ __forceinline__ void ln8(const float* sin, float* sout,
                                    const float* __restrict__ g,
                                    const float* __restrict__ bb,
                                    int warp, int lane)
{
    if (warp < 8) {
        float4 xv = *(const float4*)(sin + warp*DD + lane*4);
        float s1 = xv.x+xv.y+xv.z+xv.w;
        float s2 = fmaf(xv.x,xv.x,fmaf(xv.y,xv.y,fmaf(xv.z,xv.z,xv.w*xv.w)));
#pragma unroll
        for (int o=16;o;o>>=1){ s1+=__shfl_xor_sync(~0u,s1,o); s2+=__shfl_xor_sync(~0u,s2,o); }
        float m = s1*(1.f/DD);
        float rs = rsqrtf(fmaf(s2,1.f/DD,-m*m)+LNE);
        float4 gg = *(const float4*)(g + lane*4);
        float4 b4 = *(const float4*)(bb + lane*4);
        float4 o;
        o.x = fmaf((xv.x-m)*rs, gg.x, b4.x);
        o.y = fmaf((xv.y-m)*rs, gg.y, b4.y);
        o.z = fmaf((xv.z-m)*rs, gg.z, b4.z);
        o.w = fmaf((xv.w-m)*rs, gg.w, b4.w);
        *(float4*)(sout + warp*DD + lane*4) = o;
    }
}

__device__ __forceinline__ void mvJ(const float* __restrict__ W,
                                    const float* __restrict__ bias, int J,
                                    const float* sx, float* sout, int ldo,
                                    int warp, int nw, int lane, bool relu)
{
    for (int j = warp; j < J; j += nw) {
        float4 w4 = *(const float4*)(W + j*DD + lane*4);
        float acc[KK];
#pragma unroll
        for (int i=0;i<KK;i++){
            float4 xv = *(const float4*)(sx + i*DD + lane*4);
            acc[i] = fmaf(w4.x,xv.x,fmaf(w4.y,xv.y,fmaf(w4.z,xv.z,w4.w*xv.w)));
        }
#pragma unroll
        for (int o=16;o;o>>=1)
#pragma unroll
            for (int i=0;i<KK;i++) acc[i] += __shfl_xor_sync(~0u, acc[i], o);
        if (lane == 0) {
            float bj = bias[j];
#pragma unroll
            for (int i=0;i<KK;i++){
                float v = acc[i] + bj;
                if (relu) v = fmaxf(v, 0.f);
                sout[i*ldo + j] = v;
            }
        }
    }
}

// -------- pre: LN(slots) -> q -> qkg/sg/cb per batch --------
__global__ __launch_bounds__(512)
void pre_kernel(const float* __restrict__ slots_init, int first,
                const float* __restrict__ Wq, const float* __restrict__ bq,
                const float* __restrict__ Wk, const float* __restrict__ bk,
                const float* __restrict__ g_in, const float* __restrict__ b_in,
                const float* __restrict__ g_slot, const float* __restrict__ b_slot)
{
    const float* src = first ? slots_init : g_slots;
    int b = blockIdx.x, tid = threadIdx.x, warp = tid>>5, lane = tid&31;
    __shared__ __align__(16) float sl[KK*DD], sln[KK*DD], qb[KK*DD];
    __shared__ __align__(16) float qkg_s[KK*DD], cbt[KK*DD];
    for (int i=tid;i<KK*DD;i+=512) sl[i] = src[b*KK*DD+i];
    __syncthreads();
    ln8(sl, sln, g_slot, b_slot, warp, lane);
    __syncthreads();
    mvJ(Wq, bq, DD, sln, qb, DD, warp, 16, lane, false);
    __syncthreads();
    int i0 = tid>>7, d = tid&127;          // i0 in 0..3
    float a0=0.f, a1=0.f;
#pragma unroll 8
    for (int e=0;e<DD;e++){
        float w = Wk[e*DD+d];
        a0 = fmaf(qb[i0*DD+e], w, a0);
        a1 = fmaf(qb[(i0+4)*DD+e], w, a1);
    }
    {
        float gd = g_in[d], bd = b_in[d], bkd = bk[d];
        float qs0 = SCALE*a0, qs1 = SCALE*a1;
        float qg0 = qs0*gd,   qg1 = qs1*gd;
        qkg_s[i0*DD+d] = qg0;          qkg_s[(i0+4)*DD+d] = qg1;
        cbt[i0*DD+d]     = fmaf(qs0, bd, SCALE*qb[i0*DD+d]*bkd);
        cbt[(i0+4)*DD+d] = fmaf(qs1, bd, SCALE*qb[(i0+4)*DD+d]*bkd);
        g_qkg[(b*KK+i0)*DD + d]   = qg0;
        g_qkg[(b*KK+i0+4)*DD + d] = qg1;
    }
    __syncthreads();
    if (warp < 8){
        float s1=0.f, s2=0.f;
#pragma unroll
        for (int t=0;t<4;t++){
            s1 += qkg_s[warp*DD + lane + 32*t];
            s2 += cbt [warp*DD + lane + 32*t];
        }
#pragma unroll
        for (int o=16;o;o>>=1){ s1+=__shfl_xor_sync(~0u,s1,o); s2+=__shfl_xor_sync(~0u,s2,o); }
        if (lane==0){ g_sg[b*KK+warp] = s1; g_cb[b*KK+warp] = s2; }
    }
}

// -------- fused streaming pass over x: f32x2 packed, LN folded into dot phase ----
__global__ __launch_bounds__(256,2)
void pass_kernel(const float* __restrict__ x)
{
    const int b = blockIdx.x >> 4, chunk = blockIdx.x & (CH-1);
    const int tid = threadIdx.x, warp = tid>>5, lane = tid&31;
    const int s = lane>>2, q = lane&3;          // lane = 4*slot + quarter

    __shared__ __align__(16) float stage[8][2][152];
    __shared__ __align__(16) float red[4*KK*DD];     // 16KB tree-reduce buffer
    __shared__ float Ssh[8][KK], Tsh[8][KK];

    // qkg quarter, packed: qw[k] = {elems 4k..4k+3} of (slot s, quarter q)
    ulonglong2 qw[8];
    {
        const ulonglong2* qg = (const ulonglong2*)(g_qkg + (b*KK+s)*DD + q*32);
#pragma unroll
        for (int k=0;k<8;k++) qw[k] = qg[k];
    }
    const float sgv = g_sg[b*KK+s], cbv = g_cb[b*KK+s];

    u64 Ua[16];                                      // 8 float4 accs, packed
#pragma unroll
    for (int k=0;k<16;k++) Ua[k] = 0ull;
    float Sa = 0.f, Ta = 0.f;

    const int row0 = chunk*256 + warp*32;
    const float* xb = x + (size_t)(b*NN + row0)*DD + lane*4;
    ulonglong2 pf0 = *(const ulonglong2*)(xb);
    ulonglong2 pf1 = *(const ulonglong2*)(xb + DD);
    float* stw = &stage[warp][0][0];
    const int soff = lane*4 + (lane>>3)*8;           // elem e at e + 8*(e>>5)

    for (int r=0;r<32;r++){
        ulonglong2 xv = pf0;
        pf0 = pf1;
        if (r < 30) pf1 = *(const ulonglong2*)(xb + (size_t)(r+2)*DD);
        // stage raw row (no pre-pass LN; stats folded into dot phase)
        float* sb = stw + (r&1)*152;
        *(ulonglong2*)(sb + soff) = xv;
        __syncwarp();
        const ulonglong2* sp = (const ulonglong2*)(sb + q*40);
        u64 dA=0ull,dB=0ull, qA=0ull,qB=0ull, s2A=0ull,s2B=0ull;
#pragma unroll
        for (int k=0;k<8;k++){
            ulonglong2 xc = sp[k];
            FMA2(dA, xc.x, qw[k].x, dA);   FMA2(dB, xc.y, qw[k].y, dB);   // qkg . x
            ADD2(qA, qA, xc.x);            ADD2(qB, qB, xc.y);            // sum x
            FMA2(s2A, xc.x, xc.x, s2A);    FMA2(s2B, xc.y, xc.y, s2B);    // sum x^2
        }
        float dot, sq, ssq;
        { u64 t; float lo,hi;
          ADD2(t,dA,dB);  UNPACK2(lo,hi,t); dot = lo+hi;
          ADD2(t,qA,qB);  UNPACK2(lo,hi,t); sq  = lo+hi;
          ADD2(t,s2A,s2B);UNPACK2(lo,hi,t); ssq = lo+hi; }
        // reduce the 4 quarter-lanes of this slot (depth-2 trees, 3 values)
        dot += __shfl_xor_sync(~0u, dot, 1);  sq  += __shfl_xor_sync(~0u, sq, 1);
        ssq += __shfl_xor_sync(~0u, ssq, 1);
        dot += __shfl_xor_sync(~0u, dot, 2);  sq  += __shfl_xor_sync(~0u, sq, 2);
        ssq += __shfl_xor_sync(~0u, ssq, 2);
        float m  = sq*(1.f/DD);
        float rs = rsqrtf(fmaf(ssq,1.f/DD,-m*m)+LNE);
        // logit with LN fold; softmax over 8 slots (lane bits 2..4), max-free
        float logit = fmaf(rs, dot, fmaf(-rs*m, sgv, cbv));
        float p = __expf(logit);
        float sum = p;
#pragma unroll
        for (int o=4;o<=16;o<<=1) sum += __shfl_xor_sync(~0u, sum, o);
        float a = __fdividef(p, sum) + EPSA;
        float w = a * rs;
        Sa += a; Ta = fmaf(w, m, Ta);
        u64 w2; PACK2(w2, w, w);
#pragma unroll
        for (int k=0;k<8;k++){
            ulonglong2 xc = sp[k];
            FMA2(Ua[2*k],   w2, xc.x, Ua[2*k]);
            FMA2(Ua[2*k+1], w2, xc.y, Ua[2*k+1]);
        }
    }

    // cross-warp tree reduce 8->4->2->1 through 16KB buffer (conflict-free layout)
#pragma unroll
    for (int stride=4; stride>=1; stride>>=1){
        if (warp >= stride && warp < 2*stride){
            float* dst = red + (warp-stride)*KK*DD;
#pragma unroll
            for (int k=0;k<8;k++)
                *(ulonglong2*)(dst + k*128 + lane*4) = make_ulonglong2(Ua[2*k], Ua[2*k+1]);
        }
        __syncthreads();
        if (warp < stride){
            const float* srcp = red + warp*KK*DD;
#pragma unroll
            for (int k=0;k<8;k++){
                ulonglong2 v = *(const ulonglong2*)(srcp + k*128 + lane*4);
                ADD2(Ua[2*k],   Ua[2*k],   v.x);
                ADD2(Ua[2*k+1], Ua[2*k+1], v.y);
            }
        }
        __syncthreads();
    }
    if (warp == 0){
        float* dst = g_Up + (size_t)(b*CH+chunk)*KK*DD;
#pragma unroll
        for (int k=0;k<8;k++)
            *(ulonglong2*)(dst + s*DD + q*32 + 4*k) = make_ulonglong2(Ua[2*k], Ua[2*k+1]);
    }
    if (q == 0){ Ssh[warp][s] = Sa; Tsh[warp][s] = Ta; }
    __syncthreads();
    if (tid < KK){
        float ss=0.f, tt=0.f;
#pragma unroll
        for (int w2=0;w2<8;w2++){ ss += Ssh[w2][tid]; tt += Tsh[w2][tid]; }
        g_Sp[(b*CH+chunk)*KK + tid] = ss;
        g_Tp[(b*CH+chunk)*KK + tid] = tt;
    }
}

// -------- post: updates -> GRU -> MLP residual (512 threads) --------
__global__ __launch_bounds__(512)
void post_kernel(const float* __restrict__ slots_init, int first,
                 float* __restrict__ out, int last,
                 const float* __restrict__ Wv, const float* __restrict__ bv,
                 const float* __restrict__ g_in, const float* __restrict__ b_in,
                 const float* __restrict__ g_mlp, const float* __restrict__ b_mlp,
                 const float* __restrict__ W1, const float* __restrict__ b1,
                 const float* __restrict__ W2, const float* __restrict__ b2,
                 const float* __restrict__ W_ih, const float* __restrict__ W_hh,
                 const float* __restrict__ b_ih, const float* __restrict__ b_hh)
{
    const float* prevsrc = first ? slots_init : g_slots;
    float* dst = last ? out : g_slots;
    int b = blockIdx.x, tid = threadIdx.x, warp = tid>>5, lane = tid&31;
    __shared__ __align__(16) float Y[KK*DD], upd[KK*DD], prev[KK*DD];
    __shared__ __align__(16) float gi[KK*384], gh[KK*384];
    __shared__ float Sv[KK], Tv[KK];

    if (tid < KK){
        float ss=0.f, tt=0.f;
#pragma unroll
        for (int c=0;c<CH;c++){ ss += g_Sp[(b*CH+c)*KK+tid]; tt += g_Tp[(b*CH+c)*KK+tid]; }
        Sv[tid]=ss; Tv[tid]=tt;
    }
    __syncthreads();
    for (int idx=tid; idx<KK*DD; idx+=512){
        int i = idx>>7, d = idx&127;
        float u = 0.f;
#pragma unroll
        for (int c=0;c<CH;c++) u += g_Up[(size_t)(b*CH+c)*KK*DD + idx];
        Y[idx] = fmaf(g_in[d], (u - Tv[i]) / Sv[i], b_in[d]);
        prev[idx] = prevsrc[b*KK*DD + idx];
    }
    __syncthreads();
    mvJ(Wv, bv, DD, Y, upd, DD, warp, 16, lane, false);
    __syncthreads();
    mvJ(W_ih, b_ih, 3*DD, upd, gi, 3*DD, warp, 16, lane, false);
    mvJ(W_hh, b_hh, 3*DD, prev, gh, 3*DD, warp, 16, lane, false);
    __syncthreads();
    for (int idx=tid; idx<KK*DD; idx+=512){
        int i = idx>>7, d = idx&127;
        float r  = 1.f/(1.f+__expf(-(gi[i*384+d]       + gh[i*384+d])));
        float z  = 1.f/(1.f+__expf(-(gi[i*384+128+d]   + gh[i*384+128+d])));
        float n  = tanhf(fmaf(r, gh[i*384+256+d], gi[i*384+256+d]));
        prev[idx] = fmaf(z, prev[idx]-n, n);
    }
    __syncthreads();
    ln8(prev, Y, g_mlp, b_mlp, warp, lane);
    __syncthreads();
    mvJ(W1, b1, DD, Y, upd, DD, warp, 16, lane, true);
    __syncthreads();
    mvJ(W2, b2, DD, upd, Y, DD, warp, 16, lane, false);
    __syncthreads();
    for (int idx=tid; idx<KK*DD; idx+=512)
        dst[b*KK*DD + idx] = prev[idx] + Y[idx];
}

extern "C" void kernel_launch(void* const* d_in, const int* in_sizes, int n_in,
                              void* d_out, int out_size)
{
    const float* x          = (const float*)d_in[0];
    const float* slots_init = (const float*)d_in[1];
    const float* Wq  = (const float*)d_in[2];  const float* bq  = (const float*)d_in[3];
    const float* Wk  = (const float*)d_in[4];  const float* bk  = (const float*)d_in[5];
    const float* Wv  = (const float*)d_in[6];  const float* bv  = (const float*)d_in[7];
    const float* gin = (const float*)d_in[8];  const float* bin = (const float*)d_in[9];
    const float* gsl = (const float*)d_in[10]; const float* bsl = (const float*)d_in[11];
    const float* gml = (const float*)d_in[12]; const float* bml = (const float*)d_in[13];
    const float* W1  = (const float*)d_in[14]; const float* b1  = (const float*)d_in[15];
    const float* W2  = (const float*)d_in[16]; const float* b2  = (const float*)d_in[17];
    const float* Wih = (const float*)d_in[18]; const float* Whh = (const float*)d_in[19];
    const float* bih = (const float*)d_in[20]; const float* bhh = (const float*)d_in[21];
    float* out = (float*)d_out;

    for (int it = 0; it < 3; ++it){
        pre_kernel<<<BB, 512>>>(slots_init, it==0, Wq, bq, Wk, bk, gin, bin, gsl, bsl);
        pass_kernel<<<BB*CH, 256>>>(x);
        post_kernel<<<BB, 512>>>(slots_init, it==0, out, it==2,
                                 Wv, bv, gin, bin, gml, bml,
                                 W1, b1, W2, b2, Wih, Whh, bih, bhh);
    }
}